// round 13
// baseline (speedup 1.0000x reference)
#include <cuda_runtime.h>
#include <cuda_fp16.h>
#include <mma.h>

#define NN 50000
#define NNP 50048                                 // padded rows (128*391) for wmma A loads
#define NE 800000
#define SCAN_B 512
#define SCAN_NBLK ((NN + SCAN_B - 1) / SCAN_B)   // 98

// ---------------- packed f32x2 helpers (FFMA2 — only reachable via PTX) ----------------
__device__ __forceinline__ unsigned long long pk2(float a, float b) {
    unsigned long long r;
    asm("mov.b64 %0, {%1, %2};" : "=l"(r) : "f"(a), "f"(b));
    return r;
}
__device__ __forceinline__ void fma2(unsigned long long& d, unsigned long long a, unsigned long long b) {
    asm("fma.rn.f32x2 %0, %1, %2, %0;" : "+l"(d) : "l"(a), "l"(b));
}
__device__ __forceinline__ float2 upk2(unsigned long long v) {
    float2 r;
    asm("mov.b64 {%0, %1}, %2;" : "=f"(r.x), "=f"(r.y) : "l"(v));
    return r;
}

// ---------------- scratch (static device globals; no allocs) ----------------
// NOTE: __device__ globals are zero-initialized at module load. g_deg/g_cnt are
// re-zeroed at the END of each launch (final k_prop8), so no k_zero kernel needed.
__device__ float g_ew[NE];
__device__ float g_deg[NN];
__device__ float g_dinv[NN];
__device__ int   g_cnt[NN];
__device__ int   g_rowptr[NN + 1];
__device__ int   g_cur[NN];
__device__ int2  g_csr[NE];          // interleaved {src, __float_as_int(w)}
__device__ int   g_psum[SCAN_NBLK];
// fp32 buffers [NN x 64]: 3,4 = mid1-out / Y; 0,1 = prop8 temps
struct alignas(16) NFBuf { float v[5][NN * 64]; };
__device__ NFBuf g_nf;
// fp16 F=64 buffers [NNP x 64]: 0 = layer0 seed, 1..3 = hops, 4 = mid0 seed
struct alignas(16) NH64 { __half2 v[5][NNP * 32]; };
__device__ NH64 g_nh64;
// fp16 F=16 chain (layer 0): idx 0 = x fp16, 1..3 = hops  [NNP x 16]
struct alignas(16) NH16 { __half2 v[4][NNP * 8]; };
__device__ NH16 g_nh16;

// ---------------- edge MLP -> ew, plus deg & count histograms ----------------
// NOTE: edge_index is int32 (JAX x64 disabled downcasts jnp.int64 -> int32).
__global__ void k_edge(const float* __restrict__ ea, const int* __restrict__ ei,
                       const float* __restrict__ W1, const float* __restrict__ b1,
                       const float* __restrict__ W2, const float* __restrict__ b2) {
    __shared__ float sW1[512];
    __shared__ float sb1[64];
    __shared__ float sW2[64];
    __shared__ float sb2;
    for (int i = threadIdx.x; i < 512; i += blockDim.x) sW1[i] = W1[i];
    if (threadIdx.x < 64) { sb1[threadIdx.x] = b1[threadIdx.x]; sW2[threadIdx.x] = W2[threadIdx.x]; }
    if (threadIdx.x == 0) sb2 = b2[0];
    __syncthreads();

    int e = blockIdx.x * blockDim.x + threadIdx.x;
    if (e >= NE) return;

    float4 v0 = reinterpret_cast<const float4*>(ea)[e * 2];
    float4 v1 = reinterpret_cast<const float4*>(ea)[e * 2 + 1];
    float a[8] = {v0.x, v0.y, v0.z, v0.w, v1.x, v1.y, v1.z, v1.w};
    unsigned long long ad[8];
#pragma unroll
    for (int i = 0; i < 8; i++) ad[i] = pk2(a[i], a[i]);

    float ew = sb2;
#pragma unroll 4
    for (int j = 0; j < 64; j += 4) {           // j-quad: LDS.128 weight loads
        unsigned long long h2a = pk2(sb1[j],     sb1[j + 1]);
        unsigned long long h2b = pk2(sb1[j + 2], sb1[j + 3]);
#pragma unroll
        for (int i = 0; i < 8; i++) {
            float4 w4 = *reinterpret_cast<const float4*>(&sW1[i * 64 + j]);
            fma2(h2a, ad[i], pk2(w4.x, w4.y));
            fma2(h2b, ad[i], pk2(w4.z, w4.w));
        }
        float2 ha = upk2(h2a);
        float2 hb = upk2(h2b);
        ew = fmaf(fmaxf(ha.x, 0.f), sW2[j],     ew);
        ew = fmaf(fmaxf(ha.y, 0.f), sW2[j + 1], ew);
        ew = fmaf(fmaxf(hb.x, 0.f), sW2[j + 2], ew);
        ew = fmaf(fmaxf(hb.y, 0.f), sW2[j + 3], ew);
    }
    g_ew[e] = ew;
    int dst = ei[NE + e];
    atomicAdd(&g_deg[dst], ew);
    atomicAdd(&g_cnt[dst], 1);
}

// ---------------- scan pass 1: block count reduce + dinv + x->fp16 ----------------
__global__ void k_scan1(const float* __restrict__ x) {
    __shared__ int red[SCAN_B / 32];
    int b = blockIdx.x, t = threadIdx.x;
    int i = b * SCAN_B + t;
    int c = (i < NN) ? g_cnt[i] : 0;
    if (i < NN) {
        float d = g_deg[i];
        g_dinv[i] = (d > 0.f) ? rsqrtf(d) : 0.f;
        // convert x row -> fp16 seed for layer-0 hop chain
        const float4* xr = reinterpret_cast<const float4*>(x + (size_t)i * 16);
        __half2 hr[8];
#pragma unroll
        for (int q = 0; q < 4; q++) {
            float4 v = xr[q];
            hr[q * 2]     = __floats2half2_rn(v.x, v.y);
            hr[q * 2 + 1] = __floats2half2_rn(v.z, v.w);
        }
        *reinterpret_cast<int4*>(&g_nh16.v[0][(size_t)i * 8])     = *reinterpret_cast<int4*>(&hr[0]);
        *reinterpret_cast<int4*>(&g_nh16.v[0][(size_t)i * 8 + 4]) = *reinterpret_cast<int4*>(&hr[4]);
    }
    int v = c;
#pragma unroll
    for (int o = 16; o; o >>= 1) v += __shfl_down_sync(0xffffffffu, v, o);
    if ((t & 31) == 0) red[t >> 5] = v;
    __syncthreads();
    if (t == 0) {
        int s = 0;
#pragma unroll
        for (int w = 0; w < SCAN_B / 32; w++) s += red[w];
        g_psum[b] = s;
    }
}
// scan pass 2 (merged): per-block exclusive scan; block offset computed from g_psum
__global__ void k_scan3() {
    __shared__ int sc[SCAN_B];
    __shared__ int spsum[SCAN_NBLK];
    __shared__ int soff;
    int b = blockIdx.x, t = threadIdx.x;
    int i = b * SCAN_B + t;
    int c = (i < NN) ? g_cnt[i] : 0;
    sc[t] = c;
    if (t < SCAN_NBLK) spsum[t] = g_psum[t];
    __syncthreads();
    if (t == 0) {
        int s = 0;
        for (int k = 0; k < b; k++) s += spsum[k];
        soff = s;
        if (b == 0) g_rowptr[NN] = NE;   // total degree is exactly NE
    }
#pragma unroll
    for (int off = 1; off < SCAN_B; off <<= 1) {
        int v = (t >= off) ? sc[t - off] : 0;
        __syncthreads();
        sc[t] += v;
        __syncthreads();
    }
    if (i < NN) {
        int excl = sc[t] - c + soff;
        g_rowptr[i] = excl;
        g_cur[i]    = excl;
    }
}

// ---------------- fill CSR (by dst) with fused normalized weight, interleaved ---------
__global__ void k_fill(const int* __restrict__ ei) {
    int e = blockIdx.x * blockDim.x + threadIdx.x;
    if (e >= NE) return;
    int src = ei[e];
    int dst = ei[NE + e];
    float w = g_dinv[src] * g_ew[e] * g_dinv[dst];
    int pos = atomicAdd(&g_cur[dst], 1);
    g_csr[pos] = make_int2(src, __float_as_int(w));
}

// ---------------- F=64 fp16 hop: warp/node, unroll-4, fp32 accum, fp16 out -----------
__global__ void k_prop64h(int iidx, int oidx) {
    int g    = blockIdx.x * blockDim.x + threadIdx.x;
    int node = g >> 5;
    int lane = g & 31;
    if (node >= NN) return;
    const __half2* __restrict__ hin = g_nh64.v[iidx];
    __half2* __restrict__ hout = g_nh64.v[oidx];
    int beg = g_rowptr[node], end = g_rowptr[node + 1];
    float ax0 = 0.f, ay0 = 0.f, ax1 = 0.f, ay1 = 0.f;
    int p = beg;
    for (; p + 3 < end; p += 4) {
        int2 e0 = g_csr[p],     e1 = g_csr[p + 1];
        int2 e2 = g_csr[p + 2], e3 = g_csr[p + 3];
        float2 f0 = __half22float2(hin[(size_t)e0.x * 32 + lane]);
        float2 f1 = __half22float2(hin[(size_t)e1.x * 32 + lane]);
        float2 f2 = __half22float2(hin[(size_t)e2.x * 32 + lane]);
        float2 f3 = __half22float2(hin[(size_t)e3.x * 32 + lane]);
        float w0 = __int_as_float(e0.y), w1 = __int_as_float(e1.y);
        float w2 = __int_as_float(e2.y), w3 = __int_as_float(e3.y);
        ax0 = fmaf(w0, f0.x, ax0); ay0 = fmaf(w0, f0.y, ay0);
        ax1 = fmaf(w1, f1.x, ax1); ay1 = fmaf(w1, f1.y, ay1);
        ax0 = fmaf(w2, f2.x, ax0); ay0 = fmaf(w2, f2.y, ay0);
        ax1 = fmaf(w3, f3.x, ax1); ay1 = fmaf(w3, f3.y, ay1);
    }
    for (; p < end; p++) {
        int2 e0 = g_csr[p];
        float w = __int_as_float(e0.y);
        float2 f = __half22float2(hin[(size_t)e0.x * 32 + lane]);
        ax0 = fmaf(w, f.x, ax0); ay0 = fmaf(w, f.y, ay0);
    }
    hout[(size_t)node * 32 + lane] = __floats2half2_rn(ax0 + ax1, ay0 + ay1);
}

// ---------------- F=16 fp16 hop: 8 threads/node, unroll-4 ----------------
__global__ void k_prop16h(int iidx, int oidx) {
    int g    = blockIdx.x * blockDim.x + threadIdx.x;
    int node = g >> 3;
    int f    = g & 7;
    if (node >= NN) return;
    const __half2* __restrict__ hin = g_nh16.v[iidx];
    __half2* __restrict__ hout = g_nh16.v[oidx];
    int beg = g_rowptr[node], end = g_rowptr[node + 1];
    float ax0 = 0.f, ay0 = 0.f, ax1 = 0.f, ay1 = 0.f;
    int p = beg;
    for (; p + 3 < end; p += 4) {
        int2 e0 = g_csr[p],     e1 = g_csr[p + 1];
        int2 e2 = g_csr[p + 2], e3 = g_csr[p + 3];
        float2 f0 = __half22float2(hin[(size_t)e0.x * 8 + f]);
        float2 f1 = __half22float2(hin[(size_t)e1.x * 8 + f]);
        float2 f2 = __half22float2(hin[(size_t)e2.x * 8 + f]);
        float2 f3 = __half22float2(hin[(size_t)e3.x * 8 + f]);
        float w0 = __int_as_float(e0.y), w1 = __int_as_float(e1.y);
        float w2 = __int_as_float(e2.y), w3 = __int_as_float(e3.y);
        ax0 = fmaf(w0, f0.x, ax0); ay0 = fmaf(w0, f0.y, ay0);
        ax1 = fmaf(w1, f1.x, ax1); ay1 = fmaf(w1, f1.y, ay1);
        ax0 = fmaf(w2, f2.x, ax0); ay0 = fmaf(w2, f2.y, ay0);
        ax1 = fmaf(w3, f3.x, ax1); ay1 = fmaf(w3, f3.y, ay1);
    }
    for (; p < end; p++) {
        int2 e0 = g_csr[p];
        float w = __int_as_float(e0.y);
        float2 fv = __half22float2(hin[(size_t)e0.x * 8 + f]);
        ax0 = fmaf(w, fv.x, ax0); ay0 = fmaf(w, fv.y, ay0);
    }
    hout[(size_t)node * 8 + f] = __floats2half2_rn(ax0 + ax1, ay0 + ay1);
}

// F=8 Horner hop (fp32, last layer), unroll-4: out[n] = (A tin)[n] + yadd[n] (+ bias)
// zero_flag: final hop also re-zeroes g_deg/g_cnt for the next graph replay.
__global__ void k_prop8(int tin_sel, int tin_off, int tin_stride,
                        int y_sel, int y_off, int y_stride,
                        const float* __restrict__ bias,
                        float* __restrict__ ext_out, int out_sel, int zero_flag) {
    int g    = blockIdx.x * blockDim.x + threadIdx.x;
    int node = g >> 3;
    int f    = g & 7;
    if (node >= NN) return;
    if (zero_flag && f == 0) { g_deg[node] = 0.f; g_cnt[node] = 0; }
    const float* __restrict__ tin = g_nf.v[tin_sel] + tin_off;
    const float* __restrict__ ya  = g_nf.v[y_sel]  + y_off;
    float* __restrict__ outp = ext_out ? ext_out : g_nf.v[out_sel];
    int beg = g_rowptr[node], end = g_rowptr[node + 1];
    float acc0 = 0.f, acc1 = 0.f;
    int p = beg;
    for (; p + 3 < end; p += 4) {
        int2 e0 = g_csr[p],     e1 = g_csr[p + 1];
        int2 e2 = g_csr[p + 2], e3 = g_csr[p + 3];
        float v0 = __ldg(tin + (size_t)e0.x * tin_stride + f);
        float v1 = __ldg(tin + (size_t)e1.x * tin_stride + f);
        float v2 = __ldg(tin + (size_t)e2.x * tin_stride + f);
        float v3 = __ldg(tin + (size_t)e3.x * tin_stride + f);
        acc0 = fmaf(__int_as_float(e0.y), v0, acc0);
        acc1 = fmaf(__int_as_float(e1.y), v1, acc1);
        acc0 = fmaf(__int_as_float(e2.y), v2, acc0);
        acc1 = fmaf(__int_as_float(e3.y), v3, acc1);
    }
    for (; p < end; p++) {
        int2 e0 = g_csr[p];
        acc0 = fmaf(__int_as_float(e0.y), __ldg(tin + (size_t)e0.x * tin_stride + f), acc0);
    }
    float v = acc0 + acc1 + ya[(size_t)node * y_stride + f];
    if (bias) v += bias[f];
    outp[(size_t)node * 8 + f] = v;
}

// ---------------- tensor-core TAGConv GEMM (wmma m16n16k16, fp16 in / fp32 acc) ------
// out = relu([h | Ah | A2h | A3h] @ W + b). All 4 operand chunks read as fp16:
//   chunk 0 = buffer i0 (identity seed), chunks 1..3 = hop buffers.
// W (fp32 global) converted once to fp16 smem; smem reused as fp32 epilogue staging.
// Writes: fp32 out (if WF32) to g_nf.v[osel]; fp16 seed (if seedidx>=0) to g_nh64.v[seedidx].
template <int FIN, bool WF32>
__global__ void k_gemm_tc(int i0, const float* __restrict__ W,
                          const float* __restrict__ bias, int osel, int seedidx) {
    using namespace nvcuda::wmma;
    constexpr int KD = 4 * FIN;
    __shared__ __align__(32) char sraw[32768];     // max(KD*64*2, 128*64*4)
    __half* sW = reinterpret_cast<__half*>(sraw);
    float*  sO = reinterpret_cast<float*>(sraw);

    int tid  = threadIdx.x;
    int row0 = blockIdx.x * 128;

    // stage W -> fp16 smem [KD x 64] row-major
    for (int idx = tid; idx < KD * 16; idx += 256) {         // KD*64/4 float4 loads
        float4 w4 = reinterpret_cast<const float4*>(W)[idx];
        reinterpret_cast<__half2*>(sW)[idx * 2]     = __floats2half2_rn(w4.x, w4.y);
        reinterpret_cast<__half2*>(sW)[idx * 2 + 1] = __floats2half2_rn(w4.z, w4.w);
    }
    __syncthreads();

    int w  = tid >> 5;
    int wm = w >> 1;        // 0..3 -> rows wm*32..+32
    int wn = w & 1;         // 0..1 -> cols wn*32..+32

    fragment<accumulator, 16, 16, 16, float> a00, a01, a10, a11;
    fill_fragment(a00, 0.f); fill_fragment(a01, 0.f);
    fill_fragment(a10, 0.f); fill_fragment(a11, 0.f);

#pragma unroll
    for (int kk = 0; kk < KD / 16; kk++) {
        int b    = (kk * 16) / FIN;
        int koff = (kk * 16) % FIN;
        int bidx = (b == 0) ? i0 : b;
        const __half* Ab = (FIN == 64)
            ? reinterpret_cast<const __half*>(g_nh64.v[bidx])
            : reinterpret_cast<const __half*>(g_nh16.v[bidx]);
        Ab += (size_t)row0 * FIN + koff;

        fragment<matrix_a, 16, 16, 16, __half, row_major> fa0, fa1;
        load_matrix_sync(fa0, Ab + (size_t)(wm * 32) * FIN,        FIN);
        load_matrix_sync(fa1, Ab + (size_t)(wm * 32 + 16) * FIN,   FIN);
        fragment<matrix_b, 16, 16, 16, __half, row_major> fb0, fb1;
        load_matrix_sync(fb0, sW + kk * 16 * 64 + wn * 32,      64);
        load_matrix_sync(fb1, sW + kk * 16 * 64 + wn * 32 + 16, 64);

        mma_sync(a00, fa0, fb0, a00);
        mma_sync(a01, fa0, fb1, a01);
        mma_sync(a10, fa1, fb0, a10);
        mma_sync(a11, fa1, fb1, a11);
    }
    __syncthreads();   // done reading sW; reuse as fp32 staging

    store_matrix_sync(sO + (wm * 32) * 64 + wn * 32,             a00, 64, mem_row_major);
    store_matrix_sync(sO + (wm * 32) * 64 + wn * 32 + 16,        a01, 64, mem_row_major);
    store_matrix_sync(sO + (wm * 32 + 16) * 64 + wn * 32,        a10, 64, mem_row_major);
    store_matrix_sync(sO + (wm * 32 + 16) * 64 + wn * 32 + 16,   a11, 64, mem_row_major);
    __syncthreads();

    float* out = WF32 ? g_nf.v[osel] : nullptr;
    __half2* seed = (seedidx >= 0) ? g_nh64.v[seedidx] : nullptr;
    for (int idx = tid; idx < 128 * 32; idx += 256) {
        int r  = idx >> 5;
        int c2 = idx & 31;
        int gr = row0 + r;
        if (gr < NN) {
            float o0 = fmaxf(sO[r * 64 + c2 * 2]     + bias[c2 * 2],     0.f);
            float o1 = fmaxf(sO[r * 64 + c2 * 2 + 1] + bias[c2 * 2 + 1], 0.f);
            if (WF32) {
                out[(size_t)gr * 64 + c2 * 2]     = o0;
                out[(size_t)gr * 64 + c2 * 2 + 1] = o1;
            }
            if (seedidx >= 0) seed[(size_t)gr * 32 + c2] = __floats2half2_rn(o0, o1);
        }
    }
}

// ---------------- last-layer Y GEMM (f32x2, fp32): Y[n][k*8+j] = sum_i h[n][i]*Wl[k][i][j]
__global__ void k_gemmY(int isel, int osel, const float* __restrict__ Wl) {
    constexpr int BM = 128;
    constexpr int SK = 32;
    __shared__ float hst[SK][BM];
    __shared__ float ws[SK][32];

    const float* __restrict__ h = g_nf.v[isel];
    float* __restrict__ Y = g_nf.v[osel];

    int row0 = blockIdx.x * BM;
    int tid  = threadIdx.x;
    int trow = tid >> 3;
    int tcol = tid & 7;
    int myrow = row0 + tid;

    unsigned long long acc[8][2];
#pragma unroll
    for (int m = 0; m < 8; m++) { acc[m][0] = 0ull; acc[m][1] = 0ull; }

    for (int c = 0; c < 2; c++) {
        int gi0 = c * SK;
        if (myrow < NN) {
            const float4* s4 = reinterpret_cast<const float4*>(h + (size_t)myrow * 64 + gi0);
#pragma unroll
            for (int q = 0; q < SK / 4; q++) {
                float4 v = s4[q];
                hst[q * 4 + 0][tid] = v.x;
                hst[q * 4 + 1][tid] = v.y;
                hst[q * 4 + 2][tid] = v.z;
                hst[q * 4 + 3][tid] = v.w;
            }
        } else {
#pragma unroll
            for (int q = 0; q < SK; q++) hst[q][tid] = 0.f;
        }
        for (int idx = tid; idx < SK * 32; idx += BM) {
            int il = idx >> 5, cc = idx & 31;
            int k = cc >> 3, j = cc & 7;
            ws[il][cc] = Wl[k * 512 + (gi0 + il) * 8 + j];
        }
        __syncthreads();

#pragma unroll
        for (int i = 0; i < SK; i++) {
            float4 ha = *reinterpret_cast<const float4*>(&hst[i][trow * 8]);
            float4 hc = *reinterpret_cast<const float4*>(&hst[i][trow * 8 + 4]);
            unsigned long long hd[8];
            hd[0] = pk2(ha.x, ha.x); hd[1] = pk2(ha.y, ha.y);
            hd[2] = pk2(ha.z, ha.z); hd[3] = pk2(ha.w, ha.w);
            hd[4] = pk2(hc.x, hc.x); hd[5] = pk2(hc.y, hc.y);
            hd[6] = pk2(hc.z, hc.z); hd[7] = pk2(hc.w, hc.w);
            float4 w4 = *reinterpret_cast<const float4*>(&ws[i][tcol * 4]);
            unsigned long long wv0 = pk2(w4.x, w4.y);
            unsigned long long wv1 = pk2(w4.z, w4.w);
#pragma unroll
            for (int m = 0; m < 8; m++) {
                fma2(acc[m][0], hd[m], wv0);
                fma2(acc[m][1], hd[m], wv1);
            }
        }
        __syncthreads();
    }

#pragma unroll
    for (int m = 0; m < 8; m++) {
        int r = row0 + trow * 8 + m;
        if (r < NN) {
            float2 v0 = upk2(acc[m][0]);
            float2 v1 = upk2(acc[m][1]);
            float4 o = make_float4(v0.x, v0.y, v1.x, v1.y);
            *reinterpret_cast<float4*>(&Y[(size_t)r * 32 + tcol * 4]) = o;
        }
    }
}

// ---------------- launch ----------------
extern "C" void kernel_launch(void* const* d_in, const int* in_sizes, int n_in,
                              void* d_out, int out_size) {
    const float* x  = (const float*)d_in[0];
    const int*   ei = (const int*)d_in[1];     // int32! (JAX x64 disabled)
    const float* ea = (const float*)d_in[2];
    const float* W1 = (const float*)d_in[3];
    const float* b1 = (const float*)d_in[4];
    const float* W2 = (const float*)d_in[5];
    const float* b2 = (const float*)d_in[6];
    const float* Wf = (const float*)d_in[7];
    const float* bf = (const float*)d_in[8];
    const float* Wm = (const float*)d_in[9];
    const float* bm = (const float*)d_in[10];
    const float* Wl = (const float*)d_in[11];
    const float* bl = (const float*)d_in[12];
    float*       out = (float*)d_out;

    const int NB_E    = (NE + 255) / 256;
    const int NB_P64  = (NN * 32 + 255) / 256;
    const int NB_P16H = (NN * 8 + 255) / 256;
    const int NB_P8   = (NN * 8 + 255) / 256;
    const int NB_G    = (NN + 127) / 128;      // 391

    // preprocessing (g_deg/g_cnt zeroed by previous replay's last kernel / BSS init):
    // edge weights, gcn norm + x->fp16 (scan1), CSR build
    k_edge<<<NB_E, 256>>>(ea, ei, W1, b1, W2, b2);
    k_scan1<<<SCAN_NBLK, SCAN_B>>>(x);
    k_scan3<<<SCAN_NBLK, SCAN_B>>>();
    k_fill<<<NB_E, 256>>>(ei);

    // layer 0: fp16 hop chain nh16 0->1->2->3; TC GEMM (all-fp16 operands)
    // -> seed nh64.v[0] only (no fp32 out needed downstream)
    k_prop16h<<<NB_P16H, 256>>>(0, 1);
    k_prop16h<<<NB_P16H, 256>>>(1, 2);
    k_prop16h<<<NB_P16H, 256>>>(2, 3);
    k_gemm_tc<16, false><<<NB_G, 256>>>(0, Wf, bf, -1, 0);

    // mid layer 0: nh64 hops 0->1->2->3; TC GEMM reads v[0],v[1..3] -> seed v[4] only
    k_prop64h<<<NB_P64, 256>>>(0, 1);
    k_prop64h<<<NB_P64, 256>>>(1, 2);
    k_prop64h<<<NB_P64, 256>>>(2, 3);
    k_gemm_tc<64, false><<<NB_G, 256>>>(0, Wm, bm, -1, 4);

    // mid layer 1: hops from seed v[4] -> v[1],v[2],v[3]; TC GEMM reads v[4],v[1..3]
    // -> fp32 buf3 (input to last layer), no seed
    k_prop64h<<<NB_P64, 256>>>(4, 1);
    k_prop64h<<<NB_P64, 256>>>(1, 2);
    k_prop64h<<<NB_P64, 256>>>(2, 3);
    k_gemm_tc<64, true><<<NB_G, 256>>>(4, Wm + 4 * 64 * 64, bm + 64, 3, -1);

    // last layer via Horner (fp32): Y = h @ [W0|W1|W2|W3], then 3 hops at F=8
    k_gemmY<<<NB_G, 128>>>(3, 4, Wl);
    // T1 = A*Y3 + Y2   (buf0)
    k_prop8<<<NB_P8, 256>>>(4, 24, 32, 4, 16, 32, nullptr, nullptr, 0, 0);
    // T2 = A*T1 + Y1   (buf1)
    k_prop8<<<NB_P8, 256>>>(0, 0, 8, 4, 8, 32, nullptr, nullptr, 1, 0);
    // out = A*T2 + Y0 + b; also re-zero g_deg/g_cnt for next replay
    k_prop8<<<NB_P8, 256>>>(1, 0, 8, 4, 0, 32, bl, out, -1, 1);
}

// round 14
// speedup vs baseline: 1.0591x; 1.0591x over previous
#include <cuda_runtime.h>
#include <cuda_fp16.h>
#include <mma.h>

#define NN 50000
#define NNP 50048                                 // padded rows (128*391) for wmma A loads
#define NE 800000
#define SCAN_B 512
#define SCAN_NBLK ((NN + SCAN_B - 1) / SCAN_B)   // 98

// ---------------- packed f32x2 helpers (FFMA2 — only reachable via PTX) ----------------
__device__ __forceinline__ unsigned long long pk2(float a, float b) {
    unsigned long long r;
    asm("mov.b64 %0, {%1, %2};" : "=l"(r) : "f"(a), "f"(b));
    return r;
}
__device__ __forceinline__ void fma2(unsigned long long& d, unsigned long long a, unsigned long long b) {
    asm("fma.rn.f32x2 %0, %1, %2, %0;" : "+l"(d) : "l"(a), "l"(b));
}
__device__ __forceinline__ float2 upk2(unsigned long long v) {
    float2 r;
    asm("mov.b64 {%0, %1}, %2;" : "=f"(r.x), "=f"(r.y) : "l"(v));
    return r;
}

// ---------------- scratch (static device globals; no allocs) ----------------
// NOTE: __device__ globals are zero-initialized at module load. g_deg/g_cnt are
// re-zeroed at the END of each launch (final k_prop8), so no k_zero kernel needed.
__device__ float g_ew[NE];
__device__ float g_deg[NN];
__device__ float g_dinv[NN];
__device__ int   g_cnt[NN];
__device__ int   g_rowptr[NN + 1];
__device__ int   g_cur[NN];
__device__ int2  g_csr[NE];          // interleaved {src, __float_as_int(w)}
__device__ int   g_psum[SCAN_NBLK];
// fp32 buffers [NN x 64]: 3,4 = mid1-out / Y; 0,1 = prop8 temps
struct alignas(16) NFBuf { float v[5][NN * 64]; };
__device__ NFBuf g_nf;
// fp16 F=64 buffers [NNP x 64]: 0 = layer0 seed, 1..3 = hops, 4 = mid0 seed
struct alignas(16) NH64 { __half2 v[5][NNP * 32]; };
__device__ NH64 g_nh64;
// fp16 F=16 chain (layer 0): idx 0 = x fp16, 1..3 = hops  [NNP x 16]
struct alignas(16) NH16 { __half2 v[4][NNP * 8]; };
__device__ NH16 g_nh16;

// ---------------- edge MLP -> ew, plus deg & count histograms ----------------
// NOTE: edge_index is int32 (JAX x64 disabled downcasts jnp.int64 -> int32).
__global__ void k_edge(const float* __restrict__ ea, const int* __restrict__ ei,
                       const float* __restrict__ W1, const float* __restrict__ b1,
                       const float* __restrict__ W2, const float* __restrict__ b2) {
    __shared__ float sW1[512];
    __shared__ float sb1[64];
    __shared__ float sW2[64];
    __shared__ float sb2;
    for (int i = threadIdx.x; i < 512; i += blockDim.x) sW1[i] = W1[i];
    if (threadIdx.x < 64) { sb1[threadIdx.x] = b1[threadIdx.x]; sW2[threadIdx.x] = W2[threadIdx.x]; }
    if (threadIdx.x == 0) sb2 = b2[0];
    __syncthreads();

    int e = blockIdx.x * blockDim.x + threadIdx.x;
    if (e >= NE) return;

    float4 v0 = reinterpret_cast<const float4*>(ea)[e * 2];
    float4 v1 = reinterpret_cast<const float4*>(ea)[e * 2 + 1];
    float a[8] = {v0.x, v0.y, v0.z, v0.w, v1.x, v1.y, v1.z, v1.w};
    unsigned long long ad[8];
#pragma unroll
    for (int i = 0; i < 8; i++) ad[i] = pk2(a[i], a[i]);

    float ew = sb2;
#pragma unroll 8
    for (int j = 0; j < 64; j += 2) {
        unsigned long long h2 = pk2(sb1[j], sb1[j + 1]);
#pragma unroll
        for (int i = 0; i < 8; i++) {
            unsigned long long w2 = *reinterpret_cast<const unsigned long long*>(&sW1[i * 64 + j]);
            fma2(h2, ad[i], w2);
        }
        float2 h = upk2(h2);
        ew = fmaf(fmaxf(h.x, 0.f), sW2[j],     ew);
        ew = fmaf(fmaxf(h.y, 0.f), sW2[j + 1], ew);
    }
    g_ew[e] = ew;
    int dst = ei[NE + e];
    atomicAdd(&g_deg[dst], ew);
    atomicAdd(&g_cnt[dst], 1);
}

// ---------------- scan pass 1: block count reduce + dinv + x->fp16 ----------------
__global__ void k_scan1(const float* __restrict__ x) {
    __shared__ int red[SCAN_B / 32];
    int b = blockIdx.x, t = threadIdx.x;
    int i = b * SCAN_B + t;
    int c = (i < NN) ? g_cnt[i] : 0;
    if (i < NN) {
        float d = g_deg[i];
        g_dinv[i] = (d > 0.f) ? rsqrtf(d) : 0.f;
        // convert x row -> fp16 seed for layer-0 hop chain
        const float4* xr = reinterpret_cast<const float4*>(x + (size_t)i * 16);
        __half2 hr[8];
#pragma unroll
        for (int q = 0; q < 4; q++) {
            float4 v = xr[q];
            hr[q * 2]     = __floats2half2_rn(v.x, v.y);
            hr[q * 2 + 1] = __floats2half2_rn(v.z, v.w);
        }
        *reinterpret_cast<int4*>(&g_nh16.v[0][(size_t)i * 8])     = *reinterpret_cast<int4*>(&hr[0]);
        *reinterpret_cast<int4*>(&g_nh16.v[0][(size_t)i * 8 + 4]) = *reinterpret_cast<int4*>(&hr[4]);
    }
    int v = c;
#pragma unroll
    for (int o = 16; o; o >>= 1) v += __shfl_down_sync(0xffffffffu, v, o);
    if ((t & 31) == 0) red[t >> 5] = v;
    __syncthreads();
    if (t == 0) {
        int s = 0;
#pragma unroll
        for (int w = 0; w < SCAN_B / 32; w++) s += red[w];
        g_psum[b] = s;
    }
}
// scan pass 2 (merged): per-block exclusive scan; block offset computed from g_psum
__global__ void k_scan3() {
    __shared__ int sc[SCAN_B];
    __shared__ int spsum[SCAN_NBLK];
    __shared__ int soff;
    int b = blockIdx.x, t = threadIdx.x;
    int i = b * SCAN_B + t;
    int c = (i < NN) ? g_cnt[i] : 0;
    sc[t] = c;
    if (t < SCAN_NBLK) spsum[t] = g_psum[t];
    __syncthreads();
    if (t == 0) {
        int s = 0;
        for (int k = 0; k < b; k++) s += spsum[k];
        soff = s;
        if (b == 0) g_rowptr[NN] = NE;   // total degree is exactly NE
    }
#pragma unroll
    for (int off = 1; off < SCAN_B; off <<= 1) {
        int v = (t >= off) ? sc[t - off] : 0;
        __syncthreads();
        sc[t] += v;
        __syncthreads();
    }
    if (i < NN) {
        int excl = sc[t] - c + soff;
        g_rowptr[i] = excl;
        g_cur[i]    = excl;
    }
}

// ---------------- fill CSR (by dst) with fused normalized weight, interleaved ---------
__global__ void k_fill(const int* __restrict__ ei) {
    int e = blockIdx.x * blockDim.x + threadIdx.x;
    if (e >= NE) return;
    int src = ei[e];
    int dst = ei[NE + e];
    float w = g_dinv[src] * g_ew[e] * g_dinv[dst];
    int pos = atomicAdd(&g_cur[dst], 1);
    g_csr[pos] = make_int2(src, __float_as_int(w));
}

// ---------------- F=64 fp16 hop: warp/node, fp32 accum, fp16 out ----------------
__global__ void k_prop64h(int iidx, int oidx) {
    int g    = blockIdx.x * blockDim.x + threadIdx.x;
    int node = g >> 5;
    int lane = g & 31;
    if (node >= NN) return;
    const __half2* __restrict__ hin = g_nh64.v[iidx];
    __half2* __restrict__ hout = g_nh64.v[oidx];
    int beg = g_rowptr[node], end = g_rowptr[node + 1];
    float accx = 0.f, accy = 0.f;
    int p = beg;
    for (; p + 1 < end; p += 2) {
        int2 e0 = g_csr[p], e1 = g_csr[p + 1];
        float w0 = __int_as_float(e0.y), w1 = __int_as_float(e1.y);
        float2 f0 = __half22float2(hin[(size_t)e0.x * 32 + lane]);
        float2 f1 = __half22float2(hin[(size_t)e1.x * 32 + lane]);
        accx = fmaf(w0, f0.x, accx); accy = fmaf(w0, f0.y, accy);
        accx = fmaf(w1, f1.x, accx); accy = fmaf(w1, f1.y, accy);
    }
    if (p < end) {
        int2 e0 = g_csr[p];
        float w = __int_as_float(e0.y);
        float2 f = __half22float2(hin[(size_t)e0.x * 32 + lane]);
        accx = fmaf(w, f.x, accx); accy = fmaf(w, f.y, accy);
    }
    hout[(size_t)node * 32 + lane] = __floats2half2_rn(accx, accy);
}

// ---------------- F=16 fp16 hop: 8 threads/node (half2 per thread) ----------------
__global__ void k_prop16h(int iidx, int oidx) {
    int g    = blockIdx.x * blockDim.x + threadIdx.x;
    int node = g >> 3;
    int f    = g & 7;
    if (node >= NN) return;
    const __half2* __restrict__ hin = g_nh16.v[iidx];
    __half2* __restrict__ hout = g_nh16.v[oidx];
    int beg = g_rowptr[node], end = g_rowptr[node + 1];
    float accx = 0.f, accy = 0.f;
    int p = beg;
    for (; p + 1 < end; p += 2) {
        int2 e0 = g_csr[p], e1 = g_csr[p + 1];
        float w0 = __int_as_float(e0.y), w1 = __int_as_float(e1.y);
        float2 f0 = __half22float2(hin[(size_t)e0.x * 8 + f]);
        float2 f1 = __half22float2(hin[(size_t)e1.x * 8 + f]);
        accx = fmaf(w0, f0.x, accx); accy = fmaf(w0, f0.y, accy);
        accx = fmaf(w1, f1.x, accx); accy = fmaf(w1, f1.y, accy);
    }
    if (p < end) {
        int2 e0 = g_csr[p];
        float w = __int_as_float(e0.y);
        float2 fv = __half22float2(hin[(size_t)e0.x * 8 + f]);
        accx = fmaf(w, fv.x, accx); accy = fmaf(w, fv.y, accy);
    }
    hout[(size_t)node * 8 + f] = __floats2half2_rn(accx, accy);
}

// F=8 Horner hop (fp32, last layer): out[n] = (A tin)[n] + yadd[n] (+ bias)
// zero_flag: final hop also re-zeroes g_deg/g_cnt for the next graph replay.
__global__ void k_prop8(int tin_sel, int tin_off, int tin_stride,
                        int y_sel, int y_off, int y_stride,
                        const float* __restrict__ bias,
                        float* __restrict__ ext_out, int out_sel, int zero_flag) {
    int g    = blockIdx.x * blockDim.x + threadIdx.x;
    int node = g >> 3;
    int f    = g & 7;
    if (node >= NN) return;
    if (zero_flag && f == 0) { g_deg[node] = 0.f; g_cnt[node] = 0; }
    const float* __restrict__ tin = g_nf.v[tin_sel] + tin_off;
    const float* __restrict__ ya  = g_nf.v[y_sel]  + y_off;
    float* __restrict__ outp = ext_out ? ext_out : g_nf.v[out_sel];
    int beg = g_rowptr[node], end = g_rowptr[node + 1];
    float acc0 = 0.f, acc1 = 0.f;
    int p = beg;
    for (; p + 1 < end; p += 2) {
        int2 e0 = g_csr[p], e1 = g_csr[p + 1];
        acc0 = fmaf(__int_as_float(e0.y), __ldg(tin + (size_t)e0.x * tin_stride + f), acc0);
        acc1 = fmaf(__int_as_float(e1.y), __ldg(tin + (size_t)e1.x * tin_stride + f), acc1);
    }
    if (p < end) {
        int2 e0 = g_csr[p];
        acc0 = fmaf(__int_as_float(e0.y), __ldg(tin + (size_t)e0.x * tin_stride + f), acc0);
    }
    float v = acc0 + acc1 + ya[(size_t)node * y_stride + f];
    if (bias) v += bias[f];
    outp[(size_t)node * 8 + f] = v;
}

// ---------------- tensor-core TAGConv GEMM (wmma m16n16k16, fp16 in / fp32 acc) ------
// out = relu([h | Ah | A2h | A3h] @ W + b). All 4 operand chunks read as fp16:
//   chunk 0 = buffer i0 (identity seed), chunks 1..3 = hop buffers.
// W (fp32 global) converted once to fp16 smem; smem reused as fp32 epilogue staging.
// Writes: fp32 out (if WF32) to g_nf.v[osel]; fp16 seed (if seedidx>=0) to g_nh64.v[seedidx].
template <int FIN, bool WF32>
__global__ void k_gemm_tc(int i0, const float* __restrict__ W,
                          const float* __restrict__ bias, int osel, int seedidx) {
    using namespace nvcuda::wmma;
    constexpr int KD = 4 * FIN;
    __shared__ __align__(32) char sraw[32768];     // max(KD*64*2, 128*64*4)
    __half* sW = reinterpret_cast<__half*>(sraw);
    float*  sO = reinterpret_cast<float*>(sraw);

    int tid  = threadIdx.x;
    int row0 = blockIdx.x * 128;

    // stage W -> fp16 smem [KD x 64] row-major
    for (int idx = tid; idx < KD * 16; idx += 256) {         // KD*64/4 float4 loads
        float4 w4 = reinterpret_cast<const float4*>(W)[idx];
        reinterpret_cast<__half2*>(sW)[idx * 2]     = __floats2half2_rn(w4.x, w4.y);
        reinterpret_cast<__half2*>(sW)[idx * 2 + 1] = __floats2half2_rn(w4.z, w4.w);
    }
    __syncthreads();

    int w  = tid >> 5;
    int wm = w >> 1;        // 0..3 -> rows wm*32..+32
    int wn = w & 1;         // 0..1 -> cols wn*32..+32

    fragment<accumulator, 16, 16, 16, float> a00, a01, a10, a11;
    fill_fragment(a00, 0.f); fill_fragment(a01, 0.f);
    fill_fragment(a10, 0.f); fill_fragment(a11, 0.f);

#pragma unroll
    for (int kk = 0; kk < KD / 16; kk++) {
        int b    = (kk * 16) / FIN;
        int koff = (kk * 16) % FIN;
        int bidx = (b == 0) ? i0 : b;
        const __half* Ab = (FIN == 64)
            ? reinterpret_cast<const __half*>(g_nh64.v[bidx])
            : reinterpret_cast<const __half*>(g_nh16.v[bidx]);
        Ab += (size_t)row0 * FIN + koff;

        fragment<matrix_a, 16, 16, 16, __half, row_major> fa0, fa1;
        load_matrix_sync(fa0, Ab + (size_t)(wm * 32) * FIN,        FIN);
        load_matrix_sync(fa1, Ab + (size_t)(wm * 32 + 16) * FIN,   FIN);
        fragment<matrix_b, 16, 16, 16, __half, row_major> fb0, fb1;
        load_matrix_sync(fb0, sW + kk * 16 * 64 + wn * 32,      64);
        load_matrix_sync(fb1, sW + kk * 16 * 64 + wn * 32 + 16, 64);

        mma_sync(a00, fa0, fb0, a00);
        mma_sync(a01, fa0, fb1, a01);
        mma_sync(a10, fa1, fb0, a10);
        mma_sync(a11, fa1, fb1, a11);
    }
    __syncthreads();   // done reading sW; reuse as fp32 staging

    store_matrix_sync(sO + (wm * 32) * 64 + wn * 32,             a00, 64, mem_row_major);
    store_matrix_sync(sO + (wm * 32) * 64 + wn * 32 + 16,        a01, 64, mem_row_major);
    store_matrix_sync(sO + (wm * 32 + 16) * 64 + wn * 32,        a10, 64, mem_row_major);
    store_matrix_sync(sO + (wm * 32 + 16) * 64 + wn * 32 + 16,   a11, 64, mem_row_major);
    __syncthreads();

    float* out = WF32 ? g_nf.v[osel] : nullptr;
    __half2* seed = (seedidx >= 0) ? g_nh64.v[seedidx] : nullptr;
    for (int idx = tid; idx < 128 * 32; idx += 256) {
        int r  = idx >> 5;
        int c2 = idx & 31;
        int gr = row0 + r;
        if (gr < NN) {
            float o0 = fmaxf(sO[r * 64 + c2 * 2]     + bias[c2 * 2],     0.f);
            float o1 = fmaxf(sO[r * 64 + c2 * 2 + 1] + bias[c2 * 2 + 1], 0.f);
            if (WF32) {
                out[(size_t)gr * 64 + c2 * 2]     = o0;
                out[(size_t)gr * 64 + c2 * 2 + 1] = o1;
            }
            if (seedidx >= 0) seed[(size_t)gr * 32 + c2] = __floats2half2_rn(o0, o1);
        }
    }
}

// ---------------- last-layer Y GEMM (f32x2, fp32): Y[n][k*8+j] = sum_i h[n][i]*Wl[k][i][j]
__global__ void k_gemmY(int isel, int osel, const float* __restrict__ Wl) {
    constexpr int BM = 128;
    constexpr int SK = 32;
    __shared__ float hst[SK][BM];
    __shared__ float ws[SK][32];

    const float* __restrict__ h = g_nf.v[isel];
    float* __restrict__ Y = g_nf.v[osel];

    int row0 = blockIdx.x * BM;
    int tid  = threadIdx.x;
    int trow = tid >> 3;
    int tcol = tid & 7;
    int myrow = row0 + tid;

    unsigned long long acc[8][2];
#pragma unroll
    for (int m = 0; m < 8; m++) { acc[m][0] = 0ull; acc[m][1] = 0ull; }

    for (int c = 0; c < 2; c++) {
        int gi0 = c * SK;
        if (myrow < NN) {
            const float4* s4 = reinterpret_cast<const float4*>(h + (size_t)myrow * 64 + gi0);
#pragma unroll
            for (int q = 0; q < SK / 4; q++) {
                float4 v = s4[q];
                hst[q * 4 + 0][tid] = v.x;
                hst[q * 4 + 1][tid] = v.y;
                hst[q * 4 + 2][tid] = v.z;
                hst[q * 4 + 3][tid] = v.w;
            }
        } else {
#pragma unroll
            for (int q = 0; q < SK; q++) hst[q][tid] = 0.f;
        }
        for (int idx = tid; idx < SK * 32; idx += BM) {
            int il = idx >> 5, cc = idx & 31;
            int k = cc >> 3, j = cc & 7;
            ws[il][cc] = Wl[k * 512 + (gi0 + il) * 8 + j];
        }
        __syncthreads();

#pragma unroll
        for (int i = 0; i < SK; i++) {
            float4 ha = *reinterpret_cast<const float4*>(&hst[i][trow * 8]);
            float4 hc = *reinterpret_cast<const float4*>(&hst[i][trow * 8 + 4]);
            unsigned long long hd[8];
            hd[0] = pk2(ha.x, ha.x); hd[1] = pk2(ha.y, ha.y);
            hd[2] = pk2(ha.z, ha.z); hd[3] = pk2(ha.w, ha.w);
            hd[4] = pk2(hc.x, hc.x); hd[5] = pk2(hc.y, hc.y);
            hd[6] = pk2(hc.z, hc.z); hd[7] = pk2(hc.w, hc.w);
            float4 w4 = *reinterpret_cast<const float4*>(&ws[i][tcol * 4]);
            unsigned long long wv0 = pk2(w4.x, w4.y);
            unsigned long long wv1 = pk2(w4.z, w4.w);
#pragma unroll
            for (int m = 0; m < 8; m++) {
                fma2(acc[m][0], hd[m], wv0);
                fma2(acc[m][1], hd[m], wv1);
            }
        }
        __syncthreads();
    }

#pragma unroll
    for (int m = 0; m < 8; m++) {
        int r = row0 + trow * 8 + m;
        if (r < NN) {
            float2 v0 = upk2(acc[m][0]);
            float2 v1 = upk2(acc[m][1]);
            float4 o = make_float4(v0.x, v0.y, v1.x, v1.y);
            *reinterpret_cast<float4*>(&Y[(size_t)r * 32 + tcol * 4]) = o;
        }
    }
}

// ---------------- launch ----------------
extern "C" void kernel_launch(void* const* d_in, const int* in_sizes, int n_in,
                              void* d_out, int out_size) {
    const float* x  = (const float*)d_in[0];
    const int*   ei = (const int*)d_in[1];     // int32! (JAX x64 disabled)
    const float* ea = (const float*)d_in[2];
    const float* W1 = (const float*)d_in[3];
    const float* b1 = (const float*)d_in[4];
    const float* W2 = (const float*)d_in[5];
    const float* b2 = (const float*)d_in[6];
    const float* Wf = (const float*)d_in[7];
    const float* bf = (const float*)d_in[8];
    const float* Wm = (const float*)d_in[9];
    const float* bm = (const float*)d_in[10];
    const float* Wl = (const float*)d_in[11];
    const float* bl = (const float*)d_in[12];
    float*       out = (float*)d_out;

    const int NB_E    = (NE + 255) / 256;
    const int NB_P64  = (NN * 32 + 255) / 256;
    const int NB_P16H = (NN * 8 + 255) / 256;
    const int NB_P8   = (NN * 8 + 255) / 256;
    const int NB_G    = (NN + 127) / 128;      // 391

    // preprocessing (g_deg/g_cnt zeroed by previous replay's last kernel / BSS init):
    // edge weights, gcn norm + x->fp16 (scan1), CSR build
    k_edge<<<NB_E, 256>>>(ea, ei, W1, b1, W2, b2);
    k_scan1<<<SCAN_NBLK, SCAN_B>>>(x);
    k_scan3<<<SCAN_NBLK, SCAN_B>>>();
    k_fill<<<NB_E, 256>>>(ei);

    // layer 0: fp16 hop chain nh16 0->1->2->3; TC GEMM (all-fp16 operands)
    // -> seed nh64.v[0] only (no fp32 out needed downstream)
    k_prop16h<<<NB_P16H, 256>>>(0, 1);
    k_prop16h<<<NB_P16H, 256>>>(1, 2);
    k_prop16h<<<NB_P16H, 256>>>(2, 3);
    k_gemm_tc<16, false><<<NB_G, 256>>>(0, Wf, bf, -1, 0);

    // mid layer 0: nh64 hops 0->1->2->3; TC GEMM reads v[0],v[1..3] -> seed v[4] only
    k_prop64h<<<NB_P64, 256>>>(0, 1);
    k_prop64h<<<NB_P64, 256>>>(1, 2);
    k_prop64h<<<NB_P64, 256>>>(2, 3);
    k_gemm_tc<64, false><<<NB_G, 256>>>(0, Wm, bm, -1, 4);

    // mid layer 1: hops from seed v[4] -> v[1],v[2],v[3]; TC GEMM reads v[4],v[1..3]
    // -> fp32 buf3 (input to last layer), no seed
    k_prop64h<<<NB_P64, 256>>>(4, 1);
    k_prop64h<<<NB_P64, 256>>>(1, 2);
    k_prop64h<<<NB_P64, 256>>>(2, 3);
    k_gemm_tc<64, true><<<NB_G, 256>>>(4, Wm + 4 * 64 * 64, bm + 64, 3, -1);

    // last layer via Horner (fp32): Y = h @ [W0|W1|W2|W3], then 3 hops at F=8
    k_gemmY<<<NB_G, 128>>>(3, 4, Wl);
    // T1 = A*Y3 + Y2   (buf0)
    k_prop8<<<NB_P8, 256>>>(4, 24, 32, 4, 16, 32, nullptr, nullptr, 0, 0);
    // T2 = A*T1 + Y1   (buf1)
    k_prop8<<<NB_P8, 256>>>(0, 0, 8, 4, 8, 32, nullptr, nullptr, 1, 0);
    // out = A*T2 + Y0 + b; also re-zero g_deg/g_cnt for next replay
    k_prop8<<<NB_P8, 256>>>(1, 0, 8, 4, 0, 32, bl, out, -1, 1);
}

// round 15
// speedup vs baseline: 1.0602x; 1.0010x over previous
#include <cuda_runtime.h>
#include <cuda_fp16.h>
#include <mma.h>

#define NN 50000
#define NNP 50048                                 // padded rows (128*391) for wmma A loads
#define NE 800000
#define SCAN_B 512
#define SCAN_NBLK ((NN + SCAN_B - 1) / SCAN_B)   // 98

// ---------------- packed f32x2 helpers (FFMA2 — only reachable via PTX) ----------------
__device__ __forceinline__ unsigned long long pk2(float a, float b) {
    unsigned long long r;
    asm("mov.b64 %0, {%1, %2};" : "=l"(r) : "f"(a), "f"(b));
    return r;
}
__device__ __forceinline__ void fma2(unsigned long long& d, unsigned long long a, unsigned long long b) {
    asm("fma.rn.f32x2 %0, %1, %2, %0;" : "+l"(d) : "l"(a), "l"(b));
}
__device__ __forceinline__ float2 upk2(unsigned long long v) {
    float2 r;
    asm("mov.b64 {%0, %1}, %2;" : "=f"(r.x), "=f"(r.y) : "l"(v));
    return r;
}

// ---------------- scratch (static device globals; no allocs) ----------------
// NOTE: __device__ globals are zero-initialized at module load. g_deg/g_cnt are
// re-zeroed at the END of each launch (final k_prop8), so no k_zero kernel needed.
__device__ float g_ew[NE];
__device__ int   g_rank[NE];         // edge's rank within its dst row (from k_edge atomic)
__device__ float g_deg[NN];
__device__ float g_dinv[NN];
__device__ int   g_cnt[NN];
__device__ int   g_rowptr[NN + 1];
__device__ int2  g_csr[NE];          // interleaved {src, __float_as_int(w)}
__device__ int   g_psum[SCAN_NBLK];
// fp32 buffers [NN x 64]: 3,4 = mid1-out / Y; 0,1 = prop8 temps
struct alignas(16) NFBuf { float v[5][NN * 64]; };
__device__ NFBuf g_nf;
// fp16 F=64 buffers [NNP x 64]: 0 = layer0 seed, 1..3 = hops, 4 = mid0 seed
struct alignas(16) NH64 { __half2 v[5][NNP * 32]; };
__device__ NH64 g_nh64;
// fp16 F=16 chain (layer 0): idx 0 = x fp16, 1..3 = hops  [NNP x 16]
struct alignas(16) NH16 { __half2 v[4][NNP * 8]; };
__device__ NH16 g_nh16;

// ---------------- edge MLP -> ew, plus deg & count histograms + rank capture ----------
// NOTE: edge_index is int32 (JAX x64 disabled downcasts jnp.int64 -> int32).
__global__ void k_edge(const float* __restrict__ ea, const int* __restrict__ ei,
                       const float* __restrict__ W1, const float* __restrict__ b1,
                       const float* __restrict__ W2, const float* __restrict__ b2) {
    __shared__ float sW1[512];
    __shared__ float sb1[64];
    __shared__ float sW2[64];
    __shared__ float sb2;
    for (int i = threadIdx.x; i < 512; i += blockDim.x) sW1[i] = W1[i];
    if (threadIdx.x < 64) { sb1[threadIdx.x] = b1[threadIdx.x]; sW2[threadIdx.x] = W2[threadIdx.x]; }
    if (threadIdx.x == 0) sb2 = b2[0];
    __syncthreads();

    int e = blockIdx.x * blockDim.x + threadIdx.x;
    if (e >= NE) return;

    float4 v0 = reinterpret_cast<const float4*>(ea)[e * 2];
    float4 v1 = reinterpret_cast<const float4*>(ea)[e * 2 + 1];
    float a[8] = {v0.x, v0.y, v0.z, v0.w, v1.x, v1.y, v1.z, v1.w};
    unsigned long long ad[8];
#pragma unroll
    for (int i = 0; i < 8; i++) ad[i] = pk2(a[i], a[i]);

    float ew = sb2;
#pragma unroll 4
    for (int j = 0; j < 64; j += 4) {           // j-quad: LDS.128 weight loads
        unsigned long long h2a = pk2(sb1[j],     sb1[j + 1]);
        unsigned long long h2b = pk2(sb1[j + 2], sb1[j + 3]);
#pragma unroll
        for (int i = 0; i < 8; i++) {
            float4 w4 = *reinterpret_cast<const float4*>(&sW1[i * 64 + j]);
            fma2(h2a, ad[i], pk2(w4.x, w4.y));
            fma2(h2b, ad[i], pk2(w4.z, w4.w));
        }
        float2 ha = upk2(h2a);
        float2 hb = upk2(h2b);
        ew = fmaf(fmaxf(ha.x, 0.f), sW2[j],     ew);
        ew = fmaf(fmaxf(ha.y, 0.f), sW2[j + 1], ew);
        ew = fmaf(fmaxf(hb.x, 0.f), sW2[j + 2], ew);
        ew = fmaf(fmaxf(hb.y, 0.f), sW2[j + 3], ew);
    }
    g_ew[e] = ew;
    int dst = ei[NE + e];
    atomicAdd(&g_deg[dst], ew);
    g_rank[e] = atomicAdd(&g_cnt[dst], 1);   // rank within dst row — reused by k_fill
}

// ---------------- scan pass 1: block count reduce + dinv + x->fp16 ----------------
__global__ void k_scan1(const float* __restrict__ x) {
    __shared__ int red[SCAN_B / 32];
    int b = blockIdx.x, t = threadIdx.x;
    int i = b * SCAN_B + t;
    int c = (i < NN) ? g_cnt[i] : 0;
    if (i < NN) {
        float d = g_deg[i];
        g_dinv[i] = (d > 0.f) ? rsqrtf(d) : 0.f;
        // convert x row -> fp16 seed for layer-0 hop chain
        const float4* xr = reinterpret_cast<const float4*>(x + (size_t)i * 16);
        __half2 hr[8];
#pragma unroll
        for (int q = 0; q < 4; q++) {
            float4 v = xr[q];
            hr[q * 2]     = __floats2half2_rn(v.x, v.y);
            hr[q * 2 + 1] = __floats2half2_rn(v.z, v.w);
        }
        *reinterpret_cast<int4*>(&g_nh16.v[0][(size_t)i * 8])     = *reinterpret_cast<int4*>(&hr[0]);
        *reinterpret_cast<int4*>(&g_nh16.v[0][(size_t)i * 8 + 4]) = *reinterpret_cast<int4*>(&hr[4]);
    }
    int v = c;
#pragma unroll
    for (int o = 16; o; o >>= 1) v += __shfl_down_sync(0xffffffffu, v, o);
    if ((t & 31) == 0) red[t >> 5] = v;
    __syncthreads();
    if (t == 0) {
        int s = 0;
#pragma unroll
        for (int w = 0; w < SCAN_B / 32; w++) s += red[w];
        g_psum[b] = s;
    }
}
// scan pass 2 (merged): per-block exclusive scan; block offset computed from g_psum
__global__ void k_scan3() {
    __shared__ int sc[SCAN_B];
    __shared__ int spsum[SCAN_NBLK];
    __shared__ int soff;
    int b = blockIdx.x, t = threadIdx.x;
    int i = b * SCAN_B + t;
    int c = (i < NN) ? g_cnt[i] : 0;
    sc[t] = c;
    if (t < SCAN_NBLK) spsum[t] = g_psum[t];
    __syncthreads();
    if (t == 0) {
        int s = 0;
        for (int k = 0; k < b; k++) s += spsum[k];
        soff = s;
        if (b == 0) g_rowptr[NN] = NE;   // total degree is exactly NE
    }
#pragma unroll
    for (int off = 1; off < SCAN_B; off <<= 1) {
        int v = (t >= off) ? sc[t - off] : 0;
        __syncthreads();
        sc[t] += v;
        __syncthreads();
    }
    if (i < NN) {
        g_rowptr[i] = sc[t] - c + soff;
    }
}

// ---------------- fill CSR (by dst): NO atomics — pos = rowptr[dst] + rank[e] ---------
__global__ void k_fill(const int* __restrict__ ei) {
    int e = blockIdx.x * blockDim.x + threadIdx.x;
    if (e >= NE) return;
    int src = ei[e];
    int dst = ei[NE + e];
    float w = g_dinv[src] * g_ew[e] * g_dinv[dst];
    int pos = g_rowptr[dst] + g_rank[e];
    g_csr[pos] = make_int2(src, __float_as_int(w));
}

// ---------------- F=64 fp16 hop: warp/node, fp32 accum, fp16 out ----------------
__global__ void k_prop64h(int iidx, int oidx) {
    int g    = blockIdx.x * blockDim.x + threadIdx.x;
    int node = g >> 5;
    int lane = g & 31;
    if (node >= NN) return;
    const __half2* __restrict__ hin = g_nh64.v[iidx];
    __half2* __restrict__ hout = g_nh64.v[oidx];
    int beg = g_rowptr[node], end = g_rowptr[node + 1];
    float accx = 0.f, accy = 0.f;
    int p = beg;
    for (; p + 1 < end; p += 2) {
        int2 e0 = g_csr[p], e1 = g_csr[p + 1];
        float w0 = __int_as_float(e0.y), w1 = __int_as_float(e1.y);
        float2 f0 = __half22float2(hin[(size_t)e0.x * 32 + lane]);
        float2 f1 = __half22float2(hin[(size_t)e1.x * 32 + lane]);
        accx = fmaf(w0, f0.x, accx); accy = fmaf(w0, f0.y, accy);
        accx = fmaf(w1, f1.x, accx); accy = fmaf(w1, f1.y, accy);
    }
    if (p < end) {
        int2 e0 = g_csr[p];
        float w = __int_as_float(e0.y);
        float2 f = __half22float2(hin[(size_t)e0.x * 32 + lane]);
        accx = fmaf(w, f.x, accx); accy = fmaf(w, f.y, accy);
    }
    hout[(size_t)node * 32 + lane] = __floats2half2_rn(accx, accy);
}

// ---------------- F=16 fp16 hop: 8 threads/node (half2 per thread) ----------------
__global__ void k_prop16h(int iidx, int oidx) {
    int g    = blockIdx.x * blockDim.x + threadIdx.x;
    int node = g >> 3;
    int f    = g & 7;
    if (node >= NN) return;
    const __half2* __restrict__ hin = g_nh16.v[iidx];
    __half2* __restrict__ hout = g_nh16.v[oidx];
    int beg = g_rowptr[node], end = g_rowptr[node + 1];
    float accx = 0.f, accy = 0.f;
    int p = beg;
    for (; p + 1 < end; p += 2) {
        int2 e0 = g_csr[p], e1 = g_csr[p + 1];
        float w0 = __int_as_float(e0.y), w1 = __int_as_float(e1.y);
        float2 f0 = __half22float2(hin[(size_t)e0.x * 8 + f]);
        float2 f1 = __half22float2(hin[(size_t)e1.x * 8 + f]);
        accx = fmaf(w0, f0.x, accx); accy = fmaf(w0, f0.y, accy);
        accx = fmaf(w1, f1.x, accx); accy = fmaf(w1, f1.y, accy);
    }
    if (p < end) {
        int2 e0 = g_csr[p];
        float w = __int_as_float(e0.y);
        float2 fv = __half22float2(hin[(size_t)e0.x * 8 + f]);
        accx = fmaf(w, fv.x, accx); accy = fmaf(w, fv.y, accy);
    }
    hout[(size_t)node * 8 + f] = __floats2half2_rn(accx, accy);
}

// F=8 Horner hop (fp32, last layer): out[n] = (A tin)[n] + yadd[n] (+ bias)
// zero_flag: final hop also re-zeroes g_deg/g_cnt for the next graph replay.
__global__ void k_prop8(int tin_sel, int tin_off, int tin_stride,
                        int y_sel, int y_off, int y_stride,
                        const float* __restrict__ bias,
                        float* __restrict__ ext_out, int out_sel, int zero_flag) {
    int g    = blockIdx.x * blockDim.x + threadIdx.x;
    int node = g >> 3;
    int f    = g & 7;
    if (node >= NN) return;
    if (zero_flag && f == 0) { g_deg[node] = 0.f; g_cnt[node] = 0; }
    const float* __restrict__ tin = g_nf.v[tin_sel] + tin_off;
    const float* __restrict__ ya  = g_nf.v[y_sel]  + y_off;
    float* __restrict__ outp = ext_out ? ext_out : g_nf.v[out_sel];
    int beg = g_rowptr[node], end = g_rowptr[node + 1];
    float acc0 = 0.f, acc1 = 0.f;
    int p = beg;
    for (; p + 1 < end; p += 2) {
        int2 e0 = g_csr[p], e1 = g_csr[p + 1];
        acc0 = fmaf(__int_as_float(e0.y), __ldg(tin + (size_t)e0.x * tin_stride + f), acc0);
        acc1 = fmaf(__int_as_float(e1.y), __ldg(tin + (size_t)e1.x * tin_stride + f), acc1);
    }
    if (p < end) {
        int2 e0 = g_csr[p];
        acc0 = fmaf(__int_as_float(e0.y), __ldg(tin + (size_t)e0.x * tin_stride + f), acc0);
    }
    float v = acc0 + acc1 + ya[(size_t)node * y_stride + f];
    if (bias) v += bias[f];
    outp[(size_t)node * 8 + f] = v;
}

// ---------------- tensor-core TAGConv GEMM (wmma m16n16k16, fp16 in / fp32 acc) ------
// out = relu([h | Ah | A2h | A3h] @ W + b). All 4 operand chunks read as fp16:
//   chunk 0 = buffer i0 (identity seed), chunks 1..3 = hop buffers.
// W (fp32 global) converted once to fp16 smem; smem reused as fp32 epilogue staging.
// Writes: fp32 out (if WF32) to g_nf.v[osel]; fp16 seed (if seedidx>=0) to g_nh64.v[seedidx].
template <int FIN, bool WF32>
__global__ void k_gemm_tc(int i0, const float* __restrict__ W,
                          const float* __restrict__ bias, int osel, int seedidx) {
    using namespace nvcuda::wmma;
    constexpr int KD = 4 * FIN;
    __shared__ __align__(32) char sraw[32768];     // max(KD*64*2, 128*64*4)
    __half* sW = reinterpret_cast<__half*>(sraw);
    float*  sO = reinterpret_cast<float*>(sraw);

    int tid  = threadIdx.x;
    int row0 = blockIdx.x * 128;

    // stage W -> fp16 smem [KD x 64] row-major
    for (int idx = tid; idx < KD * 16; idx += 256) {         // KD*64/4 float4 loads
        float4 w4 = reinterpret_cast<const float4*>(W)[idx];
        reinterpret_cast<__half2*>(sW)[idx * 2]     = __floats2half2_rn(w4.x, w4.y);
        reinterpret_cast<__half2*>(sW)[idx * 2 + 1] = __floats2half2_rn(w4.z, w4.w);
    }
    __syncthreads();

    int w  = tid >> 5;
    int wm = w >> 1;        // 0..3 -> rows wm*32..+32
    int wn = w & 1;         // 0..1 -> cols wn*32..+32

    fragment<accumulator, 16, 16, 16, float> a00, a01, a10, a11;
    fill_fragment(a00, 0.f); fill_fragment(a01, 0.f);
    fill_fragment(a10, 0.f); fill_fragment(a11, 0.f);

#pragma unroll
    for (int kk = 0; kk < KD / 16; kk++) {
        int b    = (kk * 16) / FIN;
        int koff = (kk * 16) % FIN;
        int bidx = (b == 0) ? i0 : b;
        const __half* Ab = (FIN == 64)
            ? reinterpret_cast<const __half*>(g_nh64.v[bidx])
            : reinterpret_cast<const __half*>(g_nh16.v[bidx]);
        Ab += (size_t)row0 * FIN + koff;

        fragment<matrix_a, 16, 16, 16, __half, row_major> fa0, fa1;
        load_matrix_sync(fa0, Ab + (size_t)(wm * 32) * FIN,        FIN);
        load_matrix_sync(fa1, Ab + (size_t)(wm * 32 + 16) * FIN,   FIN);
        fragment<matrix_b, 16, 16, 16, __half, row_major> fb0, fb1;
        load_matrix_sync(fb0, sW + kk * 16 * 64 + wn * 32,      64);
        load_matrix_sync(fb1, sW + kk * 16 * 64 + wn * 32 + 16, 64);

        mma_sync(a00, fa0, fb0, a00);
        mma_sync(a01, fa0, fb1, a01);
        mma_sync(a10, fa1, fb0, a10);
        mma_sync(a11, fa1, fb1, a11);
    }
    __syncthreads();   // done reading sW; reuse as fp32 staging

    store_matrix_sync(sO + (wm * 32) * 64 + wn * 32,             a00, 64, mem_row_major);
    store_matrix_sync(sO + (wm * 32) * 64 + wn * 32 + 16,        a01, 64, mem_row_major);
    store_matrix_sync(sO + (wm * 32 + 16) * 64 + wn * 32,        a10, 64, mem_row_major);
    store_matrix_sync(sO + (wm * 32 + 16) * 64 + wn * 32 + 16,   a11, 64, mem_row_major);
    __syncthreads();

    float* out = WF32 ? g_nf.v[osel] : nullptr;
    __half2* seed = (seedidx >= 0) ? g_nh64.v[seedidx] : nullptr;
    for (int idx = tid; idx < 128 * 32; idx += 256) {
        int r  = idx >> 5;
        int c2 = idx & 31;
        int gr = row0 + r;
        if (gr < NN) {
            float o0 = fmaxf(sO[r * 64 + c2 * 2]     + bias[c2 * 2],     0.f);
            float o1 = fmaxf(sO[r * 64 + c2 * 2 + 1] + bias[c2 * 2 + 1], 0.f);
            if (WF32) {
                out[(size_t)gr * 64 + c2 * 2]     = o0;
                out[(size_t)gr * 64 + c2 * 2 + 1] = o1;
            }
            if (seedidx >= 0) seed[(size_t)gr * 32 + c2] = __floats2half2_rn(o0, o1);
        }
    }
}

// ---------------- last-layer Y GEMM (f32x2, fp32): Y[n][k*8+j] = sum_i h[n][i]*Wl[k][i][j]
__global__ void k_gemmY(int isel, int osel, const float* __restrict__ Wl) {
    constexpr int BM = 128;
    constexpr int SK = 32;
    __shared__ float hst[SK][BM];
    __shared__ float ws[SK][32];

    const float* __restrict__ h = g_nf.v[isel];
    float* __restrict__ Y = g_nf.v[osel];

    int row0 = blockIdx.x * BM;
    int tid  = threadIdx.x;
    int trow = tid >> 3;
    int tcol = tid & 7;
    int myrow = row0 + tid;

    unsigned long long acc[8][2];
#pragma unroll
    for (int m = 0; m < 8; m++) { acc[m][0] = 0ull; acc[m][1] = 0ull; }

    for (int c = 0; c < 2; c++) {
        int gi0 = c * SK;
        if (myrow < NN) {
            const float4* s4 = reinterpret_cast<const float4*>(h + (size_t)myrow * 64 + gi0);
#pragma unroll
            for (int q = 0; q < SK / 4; q++) {
                float4 v = s4[q];
                hst[q * 4 + 0][tid] = v.x;
                hst[q * 4 + 1][tid] = v.y;
                hst[q * 4 + 2][tid] = v.z;
                hst[q * 4 + 3][tid] = v.w;
            }
        } else {
#pragma unroll
            for (int q = 0; q < SK; q++) hst[q][tid] = 0.f;
        }
        for (int idx = tid; idx < SK * 32; idx += BM) {
            int il = idx >> 5, cc = idx & 31;
            int k = cc >> 3, j = cc & 7;
            ws[il][cc] = Wl[k * 512 + (gi0 + il) * 8 + j];
        }
        __syncthreads();

#pragma unroll
        for (int i = 0; i < SK; i++) {
            float4 ha = *reinterpret_cast<const float4*>(&hst[i][trow * 8]);
            float4 hc = *reinterpret_cast<const float4*>(&hst[i][trow * 8 + 4]);
            unsigned long long hd[8];
            hd[0] = pk2(ha.x, ha.x); hd[1] = pk2(ha.y, ha.y);
            hd[2] = pk2(ha.z, ha.z); hd[3] = pk2(ha.w, ha.w);
            hd[4] = pk2(hc.x, hc.x); hd[5] = pk2(hc.y, hc.y);
            hd[6] = pk2(hc.z, hc.z); hd[7] = pk2(hc.w, hc.w);
            float4 w4 = *reinterpret_cast<const float4*>(&ws[i][tcol * 4]);
            unsigned long long wv0 = pk2(w4.x, w4.y);
            unsigned long long wv1 = pk2(w4.z, w4.w);
#pragma unroll
            for (int m = 0; m < 8; m++) {
                fma2(acc[m][0], hd[m], wv0);
                fma2(acc[m][1], hd[m], wv1);
            }
        }
        __syncthreads();
    }

#pragma unroll
    for (int m = 0; m < 8; m++) {
        int r = row0 + trow * 8 + m;
        if (r < NN) {
            float2 v0 = upk2(acc[m][0]);
            float2 v1 = upk2(acc[m][1]);
            float4 o = make_float4(v0.x, v0.y, v1.x, v1.y);
            *reinterpret_cast<float4*>(&Y[(size_t)r * 32 + tcol * 4]) = o;
        }
    }
}

// ---------------- launch ----------------
extern "C" void kernel_launch(void* const* d_in, const int* in_sizes, int n_in,
                              void* d_out, int out_size) {
    const float* x  = (const float*)d_in[0];
    const int*   ei = (const int*)d_in[1];     // int32! (JAX x64 disabled)
    const float* ea = (const float*)d_in[2];
    const float* W1 = (const float*)d_in[3];
    const float* b1 = (const float*)d_in[4];
    const float* W2 = (const float*)d_in[5];
    const float* b2 = (const float*)d_in[6];
    const float* Wf = (const float*)d_in[7];
    const float* bf = (const float*)d_in[8];
    const float* Wm = (const float*)d_in[9];
    const float* bm = (const float*)d_in[10];
    const float* Wl = (const float*)d_in[11];
    const float* bl = (const float*)d_in[12];
    float*       out = (float*)d_out;

    const int NB_E    = (NE + 255) / 256;
    const int NB_P64  = (NN * 32 + 255) / 256;
    const int NB_P16H = (NN * 8 + 255) / 256;
    const int NB_P8   = (NN * 8 + 255) / 256;
    const int NB_G    = (NN + 127) / 128;      // 391

    // preprocessing (g_deg/g_cnt zeroed by previous replay's last kernel / BSS init):
    // edge weights + rank capture, gcn norm + x->fp16 (scan1), CSR build (atomic-free)
    k_edge<<<NB_E, 256>>>(ea, ei, W1, b1, W2, b2);
    k_scan1<<<SCAN_NBLK, SCAN_B>>>(x);
    k_scan3<<<SCAN_NBLK, SCAN_B>>>();
    k_fill<<<NB_E, 256>>>(ei);

    // layer 0: fp16 hop chain nh16 0->1->2->3; TC GEMM (all-fp16 operands)
    // -> seed nh64.v[0] only (no fp32 out needed downstream)
    k_prop16h<<<NB_P16H, 256>>>(0, 1);
    k_prop16h<<<NB_P16H, 256>>>(1, 2);
    k_prop16h<<<NB_P16H, 256>>>(2, 3);
    k_gemm_tc<16, false><<<NB_G, 256>>>(0, Wf, bf, -1, 0);

    // mid layer 0: nh64 hops 0->1->2->3; TC GEMM reads v[0],v[1..3] -> seed v[4] only
    k_prop64h<<<NB_P64, 256>>>(0, 1);
    k_prop64h<<<NB_P64, 256>>>(1, 2);
    k_prop64h<<<NB_P64, 256>>>(2, 3);
    k_gemm_tc<64, false><<<NB_G, 256>>>(0, Wm, bm, -1, 4);

    // mid layer 1: hops from seed v[4] -> v[1],v[2],v[3]; TC GEMM reads v[4],v[1..3]
    // -> fp32 buf3 (input to last layer), no seed
    k_prop64h<<<NB_P64, 256>>>(4, 1);
    k_prop64h<<<NB_P64, 256>>>(1, 2);
    k_prop64h<<<NB_P64, 256>>>(2, 3);
    k_gemm_tc<64, true><<<NB_G, 256>>>(4, Wm + 4 * 64 * 64, bm + 64, 3, -1);

    // last layer via Horner (fp32): Y = h @ [W0|W1|W2|W3], then 3 hops at F=8
    k_gemmY<<<NB_G, 128>>>(3, 4, Wl);
    // T1 = A*Y3 + Y2   (buf0)
    k_prop8<<<NB_P8, 256>>>(4, 24, 32, 4, 16, 32, nullptr, nullptr, 0, 0);
    // T2 = A*T1 + Y1   (buf1)
    k_prop8<<<NB_P8, 256>>>(0, 0, 8, 4, 8, 32, nullptr, nullptr, 1, 0);
    // out = A*T2 + Y0 + b; also re-zero g_deg/g_cnt for next replay
    k_prop8<<<NB_P8, 256>>>(1, 0, 8, 4, 0, 32, bl, out, -1, 1);
}